// round 1
// baseline (speedup 1.0000x reference)
#include <cuda_runtime.h>

// ExponentialUnitNorm: out[b,c,t,f,:] = x[b,c,t,f,:] / sqrt(s[b,c,t,f])
// where s_t = 0.01*|x_t| + 0.99*s_{t-1}, s_init = init_state[f].
// B=16, C=1, T=2000, F=481. 7696 independent chains, serial over T.
//
// Strategy: one thread per (b,f) chain (perfectly coalesced across f lanes),
// manual double-buffered unroll (U=20) so ~20 independent LDG.64 are always
// in flight per warp while the serial state recurrence is computed.

#define TT 2000
#define FF 481
#define BB 16
#define UU 20
#define NCHUNK (TT / UU)   // 100, even

__global__ __launch_bounds__(64, 1)
void eun_kernel(const float2* __restrict__ x, const float* __restrict__ init,
                float2* __restrict__ out) {
    const int f = blockIdx.x * 64 + threadIdx.x;
    const int b = blockIdx.y;
    if (f >= FF) return;

    const size_t base = (size_t)b * TT * FF + f;
    const float2* px = x + base;
    float2* po = out + base;

    const float ALPHA_F = 0.99f;
    const float OMA = (float)(1.0 - 0.99);   // match reference's (1.0 - ALPHA) in f32
    const float EPSF = 1e-14f;

    float s = init[f];

    float2 bufA[UU], bufB[UU];

    // prime buffer A with chunk 0
    #pragma unroll
    for (int i = 0; i < UU; i++) bufA[i] = __ldcs(px + (size_t)i * FF);

    #pragma unroll 1
    for (int c = 0; c < NCHUNK; c += 2) {
        // prefetch chunk c+1 into B (always valid: NCHUNK is even)
        {
            const float2* pn = px + (size_t)(c + 1) * UU * FF;
            #pragma unroll
            for (int i = 0; i < UU; i++) bufB[i] = __ldcs(pn + (size_t)i * FF);
        }

        // compute + store chunk c from A
        {
            float2* poc = po + (size_t)c * UU * FF;
            #pragma unroll
            for (int i = 0; i < UU; i++) {
                float2 v = bufA[i];
                float m = fmaxf(fmaf(v.y, v.y, v.x * v.x), EPSF);
                float rm = __frsqrt_rn(m);
                float mag = m * rm;                  // sqrt(m)
                s = fmaf(OMA, mag, ALPHA_F * s);
                float r = __frsqrt_rn(s);
                float2 o; o.x = v.x * r; o.y = v.y * r;
                __stcs(poc + (size_t)i * FF, o);
            }
        }

        // prefetch chunk c+2 into A (guarded on last iteration)
        if (c + 2 < NCHUNK) {
            const float2* pn = px + (size_t)(c + 2) * UU * FF;
            #pragma unroll
            for (int i = 0; i < UU; i++) bufA[i] = __ldcs(pn + (size_t)i * FF);
        }

        // compute + store chunk c+1 from B
        {
            float2* poc = po + (size_t)(c + 1) * UU * FF;
            #pragma unroll
            for (int i = 0; i < UU; i++) {
                float2 v = bufB[i];
                float m = fmaxf(fmaf(v.y, v.y, v.x * v.x), EPSF);
                float rm = __frsqrt_rn(m);
                float mag = m * rm;
                s = fmaf(OMA, mag, ALPHA_F * s);
                float r = __frsqrt_rn(s);
                float2 o; o.x = v.x * r; o.y = v.y * r;
                __stcs(poc + (size_t)i * FF, o);
            }
        }
    }
}

extern "C" void kernel_launch(void* const* d_in, const int* in_sizes, int n_in,
                              void* d_out, int out_size) {
    const float2* x = (const float2*)d_in[0];     // [16,1,2000,481,2] f32
    const float* init = (const float*)d_in[1];    // [1,1,481,1] f32
    float2* out = (float2*)d_out;

    dim3 grid((FF + 63) / 64, BB);                // 8 x 16 = 128 CTAs, 64 thr
    eun_kernel<<<grid, 64>>>(x, init, out);
}

// round 2
// speedup vs baseline: 2.4442x; 2.4442x over previous
#include <cuda_runtime.h>

// ExponentialUnitNorm, blocked-scan formulation.
// s_t = 0.01*|x_t| + 0.99*s_{t-1};  out = x * rsqrt(s).
// B=16, C=1, T=2000, F=481.
//
// Linearity of the scan => split T into S=20 segments of L=100.
// Pass 1: per (b,seg,f) compute segment partial Bend (zero-init local scan).
// Pass 2: per (b,seg,f) rebuild s_start from preceding partials via
//         s = Bend_k + (0.99^L)*s, then replay segment and write output.
// Parallelism: 16*20*481 = 154k threads (5120 warps) vs 7696 before.

#define TT 2000
#define FF 481
#define BB 16
#define SS 20
#define LL 100          // TT / SS
#define FPAD 512

#define ALPHA_F 0.99f
#define OMA_F   0.00999999977648258209228515625f  // (float)(1.0 - 0.99)
#define EPSF    1e-14f

__device__ float g_partial[BB][SS][FPAD];

__device__ __forceinline__ float mag_of(float2 v) {
    float m = fmaxf(fmaf(v.y, v.y, v.x * v.x), EPSF);
    return m * __frsqrt_rn(m);          // sqrt(m)
}

// exact f32 pow by squaring: (0.99f)^LL, deterministic
__device__ __forceinline__ float alpha_pow_L() {
    float r = 1.0f, a = ALPHA_F;
    int e = LL;
    #pragma unroll
    for (int i = 0; i < 7; i++) {       // 2^7 > 100
        if (e & 1) r *= a;
        a *= a;
        e >>= 1;
    }
    return r;
}

__global__ __launch_bounds__(FPAD, 4)
void eun_pass1(const float2* __restrict__ x) {
    const int f = threadIdx.x;
    const int seg = blockIdx.x;
    const int b = blockIdx.y;
    if (f >= FF) return;

    const float2* px = x + ((size_t)b * TT + (size_t)seg * LL) * FF + f;

    float s = 0.0f;
    #pragma unroll 5
    for (int j = 0; j < LL; j++) {
        float2 v = __ldcs(px + (size_t)j * FF);
        s = fmaf(OMA_F, mag_of(v), ALPHA_F * s);
    }
    g_partial[b][seg][f] = s;
}

__global__ __launch_bounds__(FPAD, 4)
void eun_pass2(const float2* __restrict__ x, const float* __restrict__ init,
               float2* __restrict__ out) {
    const int f = threadIdx.x;
    const int seg = blockIdx.x;
    const int b = blockIdx.y;
    if (f >= FF) return;

    // reconstruct s at segment start (state after step seg*LL - 1)
    const float AL = alpha_pow_L();
    float s = init[f];
    for (int k = 0; k < seg; k++)
        s = fmaf(AL, s, g_partial[b][k][f]);

    const size_t base = ((size_t)b * TT + (size_t)seg * LL) * FF + f;
    const float2* px = x + base;
    float2* po = out + base;

    #pragma unroll 5
    for (int j = 0; j < LL; j++) {
        float2 v = __ldcs(px + (size_t)j * FF);
        s = fmaf(OMA_F, mag_of(v), ALPHA_F * s);
        float r = __frsqrt_rn(s);
        float2 o;
        o.x = v.x * r;
        o.y = v.y * r;
        __stcs(po + (size_t)j * FF, o);
    }
}

extern "C" void kernel_launch(void* const* d_in, const int* in_sizes, int n_in,
                              void* d_out, int out_size) {
    const float2* x = (const float2*)d_in[0];   // [16,1,2000,481,2] f32
    const float* init = (const float*)d_in[1];  // [481] f32
    float2* out = (float2*)d_out;

    dim3 grid(SS, BB);                          // 20 x 16 = 320 CTAs
    eun_pass1<<<grid, FPAD>>>(x);
    eun_pass2<<<grid, FPAD>>>(x, init, out);
}

// round 3
// speedup vs baseline: 2.9933x; 1.2246x over previous
#include <cuda_runtime.h>

// ExponentialUnitNorm, fused single-pass blocked scan with decoupled
// aggregate lookback.
// s_t = 0.01*|x_t| + 0.99*s_{t-1};  out = x * rsqrt(s).
// B=16, C=1, T=2000, F=481.
//
// Grid: (b, seg) = 16 x 100 blocks of 512 threads (thread = one f lane).
// Phase 1: local zero-init scan of L=20 steps (warms L1/L2 with the tile).
// Publish 481-vector aggregate + flag (ticket-ordered for deadlock safety).
// Phase 2: wait for earlier same-b flags, rebuild s_start via
//          s = P_k + (0.99^L) * s over k < seg (pipelined L2 loads).
// Phase 3: replay tile (L1/L2 hits) and write output.
// DRAM traffic ~= 123 MB read + 123 MB write (vs 369 MB for two-pass).

#define TT 2000
#define FF 481
#define BB 16
#define SS 100
#define LL 20          // TT / SS
#define NTHR 512

#define ALPHA_F 0.99f
#define OMA_F   0.00999999977648258209228515625f  // (float)(1.0 - 0.99)
#define EPSF    1e-14f
#define AL_SEG  0.81790693f                       // 0.99^20

__device__ float        g_partial[BB * SS * NTHR];
__device__ int          g_flag[BB * SS];
__device__ unsigned int g_ticket;

__global__ void eun_reset() {
    int i = blockIdx.x * blockDim.x + threadIdx.x;
    if (i < BB * SS) g_flag[i] = 0;
    if (i == 0) g_ticket = 0u;
}

__device__ __forceinline__ float mag_of(float2 v) {
    float m = fmaxf(fmaf(v.y, v.y, v.x * v.x), EPSF);
    return m * __frsqrt_rn(m);          // sqrt(m)
}

__global__ __launch_bounds__(NTHR, 2)
void eun_fused(const float2* __restrict__ x, const float* __restrict__ init,
               float2* __restrict__ out) {
    __shared__ unsigned int s_vb;
    const int tid = threadIdx.x;

    // ticket: virtual block id in scheduling order (deadlock-safe lookback)
    if (tid == 0) s_vb = atomicAdd(&g_ticket, 1u);
    __syncthreads();
    const int vb  = (int)s_vb;
    const int b   = vb / SS;
    const int seg = vb % SS;
    const bool valid = tid < FF;

    const size_t base = ((size_t)b * TT + (size_t)seg * LL) * FF + tid;
    const float2* px = x + base;

    // ---- phase 1: local zero-init scan (loads warm L1/L2) ----
    float s = 0.0f;
    #pragma unroll
    for (int j = 0; j < LL; j++) {
        float2 v = valid ? px[(size_t)j * FF] : make_float2(0.f, 0.f);
        s = fmaf(OMA_F, mag_of(v), ALPHA_F * s);
    }

    // ---- publish aggregate ----
    g_partial[(size_t)vb * NTHR + tid] = s;
    __threadfence();
    __syncthreads();
    if (tid == 0) atomicExch(&g_flag[vb], 1);

    // ---- phase 2: reconstruct segment-start state ----
    float st = valid ? __ldg(init + tid) : 1.0f;
    if (seg > 0) {
        const int fb = b * SS;
        // cooperative wait: thread k polls flag k (L2, bypass L1)
        for (;;) {
            int ok = 1;
            if (tid < seg) ok = __ldcg(&g_flag[fb + tid]);
            if (__syncthreads_and(ok)) break;
            __nanosleep(200);
        }
        const float* pp = g_partial + (size_t)fb * NTHR + tid;
        int k = 0;
        #pragma unroll 1
        for (; k + 8 <= seg; k += 8) {
            float p0 = __ldcg(pp + (size_t)(k + 0) * NTHR);
            float p1 = __ldcg(pp + (size_t)(k + 1) * NTHR);
            float p2 = __ldcg(pp + (size_t)(k + 2) * NTHR);
            float p3 = __ldcg(pp + (size_t)(k + 3) * NTHR);
            float p4 = __ldcg(pp + (size_t)(k + 4) * NTHR);
            float p5 = __ldcg(pp + (size_t)(k + 5) * NTHR);
            float p6 = __ldcg(pp + (size_t)(k + 6) * NTHR);
            float p7 = __ldcg(pp + (size_t)(k + 7) * NTHR);
            st = fmaf(AL_SEG, st, p0); st = fmaf(AL_SEG, st, p1);
            st = fmaf(AL_SEG, st, p2); st = fmaf(AL_SEG, st, p3);
            st = fmaf(AL_SEG, st, p4); st = fmaf(AL_SEG, st, p5);
            st = fmaf(AL_SEG, st, p6); st = fmaf(AL_SEG, st, p7);
        }
        for (; k < seg; k++)
            st = fmaf(AL_SEG, st, __ldcg(pp + (size_t)k * NTHR));
    }

    // ---- phase 3: replay tile (L1/L2 hits) and emit output ----
    float2* po = out + base;
    #pragma unroll
    for (int j = 0; j < LL; j++) {
        float2 v = valid ? px[(size_t)j * FF] : make_float2(0.f, 0.f);
        st = fmaf(OMA_F, mag_of(v), ALPHA_F * st);
        float r = __frsqrt_rn(st);
        if (valid) {
            float2 o; o.x = v.x * r; o.y = v.y * r;
            __stcs(po + (size_t)j * FF, o);
        }
    }
}

extern "C" void kernel_launch(void* const* d_in, const int* in_sizes, int n_in,
                              void* d_out, int out_size) {
    const float2* x = (const float2*)d_in[0];   // [16,1,2000,481,2] f32
    const float* init = (const float*)d_in[1];  // [481] f32
    float2* out = (float2*)d_out;

    eun_reset<<<2, 1024>>>();
    dim3 grid(SS * BB);                         // 1600 blocks, ticket-ordered
    eun_fused<<<grid, NTHR>>>(x, init, out);
}